// round 15
// baseline (speedup 1.0000x reference)
#include <cuda_runtime.h>

#define ROWS 8
#define RPT 4
#define THREADS 1024
#define D 4096

typedef unsigned long long u64;

// H-folded, pre-scaled inner matrices: C[s][n] = (B[s][n] @ H64) / 64
__device__ float g_C[2 * 64 * 64 * 64];

__device__ __forceinline__ u64 pack2(float x) {
    u64 r; asm("mov.b64 %0,{%1,%1};" : "=l"(r) : "f"(x)); return r;
}
__device__ __forceinline__ void fma2(u64& d, u64 a, u64 b) {
    asm("fma.rn.f32x2 %0,%1,%2,%3;" : "=l"(d) : "l"(a), "l"(b), "l"(d));
}
// bank-conflict-avoiding swizzle: logical (block n, col c) -> physical col
__device__ __forceinline__ int swz(int n, int c) {
    return n * 64 + (c ^ ((n & 7) << 3));
}

// ---------------- prepass: C = (B @ H64) / 64 ----------------
__global__ void prep_kernel(const float* __restrict__ innerB) {
    const int t = blockIdx.x * blockDim.x + threadIdx.x;   // row of a 64x64 block
    const float4* src = reinterpret_cast<const float4*>(innerB + (size_t)t * 64);
    float v[64];
    #pragma unroll
    for (int k = 0; k < 16; k++) {
        float4 f = src[k];
        v[4*k] = f.x; v[4*k+1] = f.y; v[4*k+2] = f.z; v[4*k+3] = f.w;
    }
    #pragma unroll
    for (int h = 1; h < 64; h <<= 1)
        #pragma unroll
        for (int m = 0; m < 64; m += 2*h)
            #pragma unroll
            for (int k = 0; k < h; k++) {
                float a = v[m+k], b = v[m+k+h];
                v[m+k] = a + b; v[m+k+h] = a - b;
            }
    float4* dst = reinterpret_cast<float4*>(g_C + (size_t)t * 64);
    const float s = 1.0f / 64.0f;
    #pragma unroll
    for (int k = 0; k < 16; k++)
        dst[k] = make_float4(v[4*k]*s, v[4*k+1]*s, v[4*k+2]*s, v[4*k+3]*s);
}

// load a 2-j slab (j0 even) of 8 cols at OBX
#define LOADC(S, BASE, STRIDE, J0, OBX)                                                     \
    S[0][0] = *reinterpret_cast<const ulonglong2*>(&(BASE)[(J0) * (STRIDE) + (OBX)]);       \
    S[0][1] = *reinterpret_cast<const ulonglong2*>(&(BASE)[(J0) * (STRIDE) + (OBX) + 4]);   \
    S[1][0] = *reinterpret_cast<const ulonglong2*>(&(BASE)[((J0) + 1) * (STRIDE) + (OBX)]); \
    S[1][1] = *reinterpret_cast<const ulonglong2*>(&(BASE)[((J0) + 1) * (STRIDE) + (OBX) + 4]);

// consume a 2-j slab against RPT rows starting at ROWB, x pair at physical col PJ
#define COMP2(S, PJ, ROWB)                                                           \
    {                                                                                \
        const int pj_ = (PJ);                                                        \
        _Pragma("unroll")                                                            \
        for (int r = 0; r < RPT; r++) {                                              \
            const float2 xp = *reinterpret_cast<const float2*>(                      \
                &sd[((ROWB) + r) * D + pj_]);                                        \
            u64 xs = pack2(xp.x);                                                    \
            fma2(acc[r][0], xs, S[0][0].x); fma2(acc[r][1], xs, S[0][0].y);          \
            fma2(acc[r][2], xs, S[0][1].x); fma2(acc[r][3], xs, S[0][1].y);          \
            xs = pack2(xp.y);                                                        \
            fma2(acc[r][0], xs, S[1][0].x); fma2(acc[r][1], xs, S[1][0].y);          \
            fma2(acc[r][2], xs, S[1][1].x); fma2(acc[r][3], xs, S[1][1].y);          \
        }                                                                            \
    }

// ---------------- main fused kernel: 1024 threads, rows split across 2 sets ----------------
__global__ __launch_bounds__(THREADS, 1)
void bh_fused_kernel(const float* __restrict__ x,
                     const float* __restrict__ finalB,
                     float* __restrict__ out)
{
    extern __shared__ float sd[];   // ROWS * D floats, swizzled layout (128 KB)
    const int tid = threadIdx.x;
    const size_t row0 = (size_t)blockIdx.x * ROWS;

    // ---- load ROWS rows (coalesced gmem read, swizzled smem store) ----
    {
        const float4* gx = reinterpret_cast<const float4*>(x + row0 * D);
        float4* s4 = reinterpret_cast<float4*>(sd);
        #pragma unroll
        for (int k = 0; k < (ROWS * D / 4) / THREADS; k++) {
            const int f   = tid + k * THREADS;
            const int r   = f >> 10;
            const int cq  = f & 1023;
            const int n   = cq >> 4;
            const int c   = (cq & 15) * 4;
            s4[r * 1024 + (swz(n, c) >> 2)] = gx[f];
        }
    }
    __syncthreads();

    const int g    = (tid >> 3) & 63;   // group 0..63 (8 threads per group)
    const int ob   = (tid & 7) * 8;     // output-col base within group
    const int rowb = (tid >> 9) * RPT;  // row set: 0..3 or 4..7
    const int pb   = swz(g, ob);

    // FWHT mapping: 128 threads per row; each owns one column x one m-half
    const int frow  = tid >> 7;         // 0..7
    const int fhalf = (tid >> 6) & 1;   // which m-half this thread OWNS (writes)
    const int fhj   = tid & 63;         // column within block
    const int fmb   = fhalf << 5;

    #pragma unroll 1
    for (int stage = 0; stage < 2; stage++) {
        // ---- block-diag 64x64 matmul with C (4 rows per thread) ----
        const float* C = g_C + ((size_t)stage * 64 + g) * 64 * 64;

        u64 acc[RPT][4];
        #pragma unroll
        for (int r = 0; r < RPT; r++)
            #pragma unroll
            for (int p = 0; p < 4; p++)
                acc[r][p] = 0ull;

        #pragma unroll 1
        for (int jb = 0; jb < 32; jb++) {
            ulonglong2 S[2][2];
            LOADC(S, C, 64, jb * 2, ob)
            COMP2(S, swz(g, jb * 2), rowb)
        }
        // block g rows rowb..rowb+3 are read/written only by this warp's set
        __syncwarp();
        #pragma unroll
        for (int r = 0; r < RPT; r++) {
            ulonglong2* sp = reinterpret_cast<ulonglong2*>(&sd[(rowb + r) * D + pb]);
            sp[0] = make_ulonglong2(acc[r][0], acc[r][1]);
            sp[1] = make_ulonglong2(acc[r][2], acc[r][3]);
        }
        __syncthreads();

        // ---- outer H64, commuted levels: h=32 first (from smem), then h=1..16 in reg ----
        {
            float v[32];
            #pragma unroll
            for (int m = 0; m < 32; m++) {
                const int co = frow * D + (fhj ^ ((m & 7) << 3));
                const float a = sd[co + m * 64];
                const float b = sd[co + (m + 32) * 64];
                v[m] = fhalf ? (a - b) : (a + b);
            }
            #pragma unroll
            for (int h = 1; h < 32; h <<= 1)
                #pragma unroll
                for (int m0 = 0; m0 < 32; m0 += 2 * h)
                    #pragma unroll
                    for (int k = 0; k < h; k++) {
                        const float a = v[m0 + k], b = v[m0 + k + h];
                        v[m0 + k]     = a + b;
                        v[m0 + k + h] = a - b;
                    }
            __syncthreads();   // all reads of old values done before overwrite
            #pragma unroll
            for (int m = 0; m < 32; m++)
                sd[frow * D + (fmb + m) * 64 + (fhj ^ ((m & 7) << 3))] = v[m];
            __syncthreads();
        }
    }

    // ---------------- final block-diag 128 x (32x32) matmul -> GMEM ----------------
    {
        const int rect = (tid >> 2) & 127;   // 4 threads per rect per row-set
        const int ob2  = (tid & 3) * 8;
        const int n    = rect >> 1;
        const int cb   = (rect & 1) * 32;
        const float* B = finalB + (size_t)rect * 32 * 32;

        u64 acc[RPT][4];
        #pragma unroll
        for (int r = 0; r < RPT; r++)
            #pragma unroll
            for (int p = 0; p < 4; p++)
                acc[r][p] = 0ull;

        #pragma unroll 1
        for (int jb = 0; jb < 16; jb++) {
            ulonglong2 S[2][2];
            LOADC(S, B, 32, jb * 2, ob2)
            COMP2(S, swz(n, cb + jb * 2), rowb)
        }
        #pragma unroll
        for (int r = 0; r < RPT; r++) {
            ulonglong2* op = reinterpret_cast<ulonglong2*>(
                out + (row0 + rowb + r) * D + rect * 32 + ob2);
            op[0] = make_ulonglong2(acc[r][0], acc[r][1]);
            op[1] = make_ulonglong2(acc[r][2], acc[r][3]);
        }
    }
}

extern "C" void kernel_launch(void* const* d_in, const int* in_sizes, int n_in,
                              void* d_out, int out_size) {
    const float* x  = (const float*)d_in[0];   // [4,4096,4096] f32
    const float* iB = (const float*)d_in[1];   // [2,64,64,64]  f32
    const float* fB = (const float*)d_in[2];   // [128,32,32]   f32
    float* out = (float*)d_out;                // [4,4096,4096] f32

    prep_kernel<<<64, 128>>>(iB);

    const int smem = ROWS * D * sizeof(float); // 131072 bytes
    cudaFuncSetAttribute(bh_fused_kernel,
                         cudaFuncAttributeMaxDynamicSharedMemorySize, smem);
    const int nrows = 4 * 4096;
    bh_fused_kernel<<<nrows / ROWS, THREADS, smem>>>(x, fB, out);
}

// round 16
// speedup vs baseline: 1.3811x; 1.3811x over previous
#include <cuda_runtime.h>

#define ROWS 8
#define THREADS 512
#define D 4096

typedef unsigned long long u64;
typedef unsigned int u32;

// H-folded, pre-scaled inner matrices: C[s][n] = (B[s][n] @ H64) / 64
__device__ float g_C[2 * 64 * 64 * 64];

__device__ __forceinline__ u64 pack2(float x) {
    u64 r; asm("mov.b64 %0,{%1,%1};" : "=l"(r) : "f"(x)); return r;
}
__device__ __forceinline__ void fma2(u64& d, u64 a, u64 b) {
    asm("fma.rn.f32x2 %0,%1,%2,%3;" : "=l"(d) : "l"(a), "l"(b), "l"(d));
}
// bank-conflict-avoiding swizzle: logical (block n, col c) -> physical col
__device__ __forceinline__ int swz(int n, int c) {
    return n * 64 + (c ^ ((n & 7) << 3));
}
__device__ __forceinline__ u32 s2u(const void* p) {
    u32 a; asm("{ .reg .u64 t; cvta.to.shared.u64 t, %1; cvt.u32.u64 %0, t; }" : "=r"(a) : "l"(p));
    return a;
}
__device__ __forceinline__ void cpa16(u32 dst, const void* src) {
    asm volatile("cp.async.ca.shared.global [%0], [%1], 16;" :: "r"(dst), "l"(src));
}

// ---------------- prepass: C = (B @ H64) / 64 ----------------
__global__ void prep_kernel(const float* __restrict__ innerB) {
    const int t = blockIdx.x * blockDim.x + threadIdx.x;   // row of a 64x64 block
    const float4* src = reinterpret_cast<const float4*>(innerB + (size_t)t * 64);
    float v[64];
    #pragma unroll
    for (int k = 0; k < 16; k++) {
        float4 f = src[k];
        v[4*k] = f.x; v[4*k+1] = f.y; v[4*k+2] = f.z; v[4*k+3] = f.w;
    }
    #pragma unroll
    for (int h = 1; h < 64; h <<= 1)
        #pragma unroll
        for (int m = 0; m < 64; m += 2*h)
            #pragma unroll
            for (int k = 0; k < h; k++) {
                float a = v[m+k], b = v[m+k+h];
                v[m+k] = a + b; v[m+k+h] = a - b;
            }
    float4* dst = reinterpret_cast<float4*>(g_C + (size_t)t * 64);
    const float s = 1.0f / 64.0f;
    #pragma unroll
    for (int k = 0; k < 16; k++)
        dst[k] = make_float4(v[4*k]*s, v[4*k+1]*s, v[4*k+2]*s, v[4*k+3]*s);
}

// load a 2-j slab (j0 even): S[0] = row j0 cols[OBX..OBX+8), S[1] = row j0+1
#define LOADC(S, BASE, STRIDE, J0, OBX)                                                     \
    S[0][0] = *reinterpret_cast<const ulonglong2*>(&(BASE)[(J0) * (STRIDE) + (OBX)]);       \
    S[0][1] = *reinterpret_cast<const ulonglong2*>(&(BASE)[(J0) * (STRIDE) + (OBX) + 4]);   \
    S[1][0] = *reinterpret_cast<const ulonglong2*>(&(BASE)[((J0) + 1) * (STRIDE) + (OBX)]); \
    S[1][1] = *reinterpret_cast<const ulonglong2*>(&(BASE)[((J0) + 1) * (STRIDE) + (OBX) + 4]);

// consume a 2-j slab against x pair at physical col PJ
#define COMP2(S, PJ)                                                                 \
    {                                                                                \
        const int pj_ = (PJ);                                                        \
        _Pragma("unroll")                                                            \
        for (int r = 0; r < ROWS; r++) {                                             \
            const float2 xp = *reinterpret_cast<const float2*>(&sd[r * D + pj_]);    \
            u64 xs = pack2(xp.x);                                                    \
            fma2(acc[r][0], xs, S[0][0].x); fma2(acc[r][1], xs, S[0][0].y);          \
            fma2(acc[r][2], xs, S[0][1].x); fma2(acc[r][3], xs, S[0][1].y);          \
            xs = pack2(xp.y);                                                        \
            fma2(acc[r][0], xs, S[1][0].x); fma2(acc[r][1], xs, S[1][0].y);          \
            fma2(acc[r][2], xs, S[1][1].x); fma2(acc[r][3], xs, S[1][1].y);          \
        }                                                                            \
    }

// ---------------- main fused kernel ----------------
__global__ __launch_bounds__(THREADS, 1)
void bh_fused_kernel(const float* __restrict__ x,
                     const float* __restrict__ finalB,
                     float* __restrict__ out)
{
    extern __shared__ float sd[];   // ROWS * D floats, swizzled layout
    const int tid = threadIdx.x;
    const size_t row0 = (size_t)blockIdx.x * ROWS;
    const u32 sbase = s2u(sd);

    // ---- async load of ROWS rows (cp.async, swizzled destinations) ----
    {
        const float4* gx = reinterpret_cast<const float4*>(x + row0 * D);
        #pragma unroll
        for (int k = 0; k < (ROWS * D / 4) / THREADS; k++) {
            const int f   = tid + k * THREADS;
            const int r   = f >> 10;
            const int cq  = f & 1023;
            const int n   = cq >> 4;
            const int c   = (cq & 15) * 4;
            const u32 doff = (u32)(r * 1024 + (swz(n, c) >> 2)) * 16;
            cpa16(sbase + doff, gx + f);
        }
        asm volatile("cp.async.commit_group;" ::: "memory");
    }

    const int g  = tid >> 3;         // group 0..63 (8 threads per group)
    const int ob = (tid & 7) * 8;    // output-col base within group
    const int pb = swz(g, ob);       // physical col base for writes (8-aligned)

    // final-matmul mapping (computed early for the cross-phase prefetch)
    const int rect = tid >> 2;        // 0..127 (4 threads per rect)
    const int ob2  = (tid & 3) * 8;
    const int nf   = rect >> 1;
    const int cbf  = (rect & 1) * 32;
    const float* Bfin = finalB + (size_t)rect * 32 * 32;

    const float* C0 = g_C + (size_t)g * 4096;
    const float* C1 = g_C + (size_t)(64 + g) * 4096;

    // prefetch stage-0 slab 0 while the x tile streams in
    ulonglong2 A[2][2], Bv[2][2];
    LOADC(A, C0, 64, 0, ob)

    asm volatile("cp.async.wait_group 0;" ::: "memory");
    __syncthreads();

    #pragma unroll 1
    for (int stage = 0; stage < 2; stage++) {
        const float* C = stage ? C1 : C0;

        u64 acc[ROWS][4];
        #pragma unroll
        for (int r = 0; r < ROWS; r++)
            #pragma unroll
            for (int p = 0; p < 4; p++)
                acc[r][p] = 0ull;

        // A already holds this stage's slab 0 (prefetched before the barrier)
        #pragma unroll 2
        for (int sb = 0; sb < 16; sb++) {
            const int j0 = sb * 4;
            LOADC(Bv, C, 64, j0 + 2, ob)                // j+2, j+3
            COMP2(A, swz(g, j0))                        // consume j, j+1
            if (sb < 15) { LOADC(A, C, 64, j0 + 4, ob) }// j+4, j+5
            COMP2(Bv, swz(g, j0 + 2))                   // consume j+2, j+3
        }
        // block g's region is read/written only by its own group (one warp)
        __syncwarp();
        #pragma unroll
        for (int r = 0; r < ROWS; r++) {
            ulonglong2* sp = reinterpret_cast<ulonglong2*>(&sd[r * D + pb]);
            sp[0] = make_ulonglong2(acc[r][0], acc[r][1]);
            sp[1] = make_ulonglong2(acc[r][2], acc[r][3]);
        }
        __syncthreads();

        // ---- outer H64 (stride-64 across blocks), register-resident ----
        {
            const int hr = tid >> 6;      // row 0..7
            const int hj = tid & 63;      // within-block column
            float v[64];
            #pragma unroll
            for (int m = 0; m < 64; m++)
                v[m] = sd[hr * D + m * 64 + (hj ^ ((m & 7) << 3))];
            #pragma unroll
            for (int h = 1; h < 64; h <<= 1)
                #pragma unroll
                for (int m0 = 0; m0 < 64; m0 += 2*h)
                    #pragma unroll
                    for (int k = 0; k < h; k++) {
                        float a = v[m0+k], b = v[m0+k+h];
                        v[m0+k] = a + b; v[m0+k+h] = a - b;
                    }
            #pragma unroll
            for (int m = 0; m < 64; m++)
                sd[hr * D + m * 64 + (hj ^ ((m & 7) << 3))] = v[m];
        }

        // cross-phase prefetch of the NEXT phase's slab 0 (v[] dead, regs free)
        if (stage == 0) { LOADC(A, C1, 64, 0, ob) }
        else            { LOADC(A, Bfin, 32, 0, ob2) }
        __syncthreads();
    }

    // ---------------- final block-diag 128 x (32x32) matmul -> GMEM ----------------
    {
        u64 acc[ROWS][4];
        #pragma unroll
        for (int r = 0; r < ROWS; r++)
            #pragma unroll
            for (int p = 0; p < 4; p++)
                acc[r][p] = 0ull;

        // A already holds finalB slab 0 (prefetched before the barrier)
        #pragma unroll 2
        for (int sb = 0; sb < 8; sb++) {
            const int j0 = sb * 4;
            LOADC(Bv, Bfin, 32, j0 + 2, ob2)
            COMP2(A, swz(nf, cbf + j0))
            if (sb < 7) { LOADC(A, Bfin, 32, j0 + 4, ob2) }
            COMP2(Bv, swz(nf, cbf + j0 + 2))
        }
        #pragma unroll
        for (int r = 0; r < ROWS; r++) {
            ulonglong2* op = reinterpret_cast<ulonglong2*>(out + (row0 + r) * D + rect * 32 + ob2);
            op[0] = make_ulonglong2(acc[r][0], acc[r][1]);
            op[1] = make_ulonglong2(acc[r][2], acc[r][3]);
        }
    }
}

extern "C" void kernel_launch(void* const* d_in, const int* in_sizes, int n_in,
                              void* d_out, int out_size) {
    const float* x  = (const float*)d_in[0];   // [4,4096,4096] f32
    const float* iB = (const float*)d_in[1];   // [2,64,64,64]  f32
    const float* fB = (const float*)d_in[2];   // [128,32,32]   f32
    float* out = (float*)d_out;                // [4,4096,4096] f32

    prep_kernel<<<64, 128>>>(iB);

    const int smem = ROWS * D * sizeof(float); // 131072 bytes
    cudaFuncSetAttribute(bh_fused_kernel,
                         cudaFuncAttributeMaxDynamicSharedMemorySize, smem);
    const int nrows = 4 * 4096;
    bh_fused_kernel<<<nrows / ROWS, THREADS, smem>>>(x, fB, out);
}